// round 3
// baseline (speedup 1.0000x reference)
#include <cuda_runtime.h>
#include <cuda_bf16.h>
#include <math.h>
#include <limits.h>

#define N_NODES 100000
#define N_EDGES 1600000
#define NFEAT 128
#define NHID 32
#define NCLASS 40
#define NEG_SLOPE 0.2f

// ---------------- scratch ----------------------------------------------------
__device__ __align__(16) float g_h1[N_NODES * NHID];    // layer1 node features
__device__ __align__(16) float g_x2[N_NODES * NHID];    // layer1 output
__device__ __align__(16) float g_h2[N_NODES * NCLASS];  // layer2 node features
__device__ float g_asrc[N_NODES];
__device__ float g_adst[N_NODES];
// CSR by destination
__device__ int g_deg[N_NODES];
__device__ int g_rowptr[N_NODES + 1];
__device__ int g_cursor[N_NODES];
__device__ int g_srcs[N_EDGES];

__device__ __forceinline__ float lrelu(float x) {
    return x > 0.f ? x : NEG_SLOPE * x;
}

// ---------------- CSR build --------------------------------------------------
__global__ void zero_deg_kernel() {
    int i = blockIdx.x * blockDim.x + threadIdx.x;
    if (i < N_NODES) g_deg[i] = 0;
}

__global__ void hist_kernel(const int* __restrict__ dst) {
    int e = blockIdx.x * blockDim.x + threadIdx.x;
    if (e < N_EDGES) atomicAdd(&g_deg[dst[e]], 1);
}

// single-block exclusive scan of g_deg -> g_rowptr / g_cursor
__global__ void scan_kernel() {
    const int T = 1024;
    const int CHUNK = (N_NODES + T - 1) / T;  // 98
    __shared__ int ssum[T];
    int t = threadIdx.x;
    int lo = t * CHUNK;
    int hi = min(lo + CHUNK, N_NODES);
    int local = 0;
    for (int i = lo; i < hi; i++) local += g_deg[i];
    ssum[t] = local;
    __syncthreads();
    // Hillis-Steele inclusive scan
    for (int off = 1; off < T; off <<= 1) {
        int v = (t >= off) ? ssum[t - off] : 0;
        __syncthreads();
        ssum[t] += v;
        __syncthreads();
    }
    int run = ssum[t] - local;  // exclusive base for this thread's chunk
    for (int i = lo; i < hi; i++) {
        g_rowptr[i] = run;
        g_cursor[i] = run;
        run += g_deg[i];
    }
    if (t == 0) g_rowptr[N_NODES] = N_EDGES;
}

__global__ void scatter_kernel(const int* __restrict__ src,
                               const int* __restrict__ dst) {
    int e = blockIdx.x * blockDim.x + threadIdx.x;
    if (e >= N_EDGES) return;
    int d = dst[e];
    int pos = atomicAdd(&g_cursor[d], 1);
    g_srcs[pos] = src[e];
}

// ---------------- layer 1 GEMM: h1 = x @ W1, + alpha_src/dst ----------------
__global__ void gemm1_kernel(const float* __restrict__ x,
                             const float* __restrict__ W1,
                             const float* __restrict__ a_src,
                             const float* __restrict__ a_dst) {
    __shared__ float Wsh[NFEAT * NHID];
    __shared__ float xsh[32][NFEAT];
    __shared__ float as[NHID], ad[NHID];
    int tid = threadIdx.x;
    int base = blockIdx.x * 32;

    for (int i = tid; i < NFEAT * NHID; i += 256) Wsh[i] = W1[i];
    if (tid < NHID) { as[tid] = a_src[tid]; ad[tid] = a_dst[tid]; }
    for (int i = tid; i < 32 * NFEAT; i += 256) {
        int r = i >> 7, cc = i & 127;
        xsh[r][cc] = x[(size_t)(base + r) * NFEAT + cc];
    }
    __syncthreads();

    int c = tid & 31, rr = tid >> 5;
    float acc[4] = {0.f, 0.f, 0.f, 0.f};
    #pragma unroll 8
    for (int k = 0; k < NFEAT; k++) {
        float wk = Wsh[k * NHID + c];
        acc[0] += xsh[rr     ][k] * wk;
        acc[1] += xsh[rr +  8][k] * wk;
        acc[2] += xsh[rr + 16][k] * wk;
        acc[3] += xsh[rr + 24][k] * wk;
    }
    #pragma unroll
    for (int j = 0; j < 4; j++) {
        int n = base + rr + 8 * j;
        g_h1[n * NHID + c] = acc[j];
        float av = acc[j] * as[c];
        float dv = acc[j] * ad[c];
        #pragma unroll
        for (int o = 16; o > 0; o >>= 1) {
            av += __shfl_xor_sync(0xffffffffu, av, o);
            dv += __shfl_xor_sync(0xffffffffu, dv, o);
        }
        if (c == 0) { g_asrc[n] = av; g_adst[n] = dv; }
    }
}

// ---------------- layer 2 GEMM ----------------------------------------------
__global__ void gemm2_kernel(const float* __restrict__ W2,
                             const float* __restrict__ a_src,
                             const float* __restrict__ a_dst) {
    __shared__ float Wsh[NHID * NCLASS];
    __shared__ float as[NCLASS], ad[NCLASS];
    int tid = threadIdx.x;
    for (int i = tid; i < NHID * NCLASS; i += 256) Wsh[i] = W2[i];
    if (tid < NCLASS) { as[tid] = a_src[tid]; ad[tid] = a_dst[tid]; }
    __syncthreads();

    int lane = tid & 31, w = tid >> 5;
    int n = blockIdx.x * 8 + w;
    float hval = g_x2[n * NHID + lane];
    bool act1 = lane < 8;
    int c0 = lane;
    int c1 = act1 ? lane + 32 : 0;
    float acc0 = 0.f, acc1 = 0.f;
    #pragma unroll
    for (int k = 0; k < NHID; k++) {
        float hk = __shfl_sync(0xffffffffu, hval, k);
        acc0 += hk * Wsh[k * NCLASS + c0];
        acc1 += hk * Wsh[k * NCLASS + c1];
    }
    g_h2[n * NCLASS + c0] = acc0;
    if (act1) g_h2[n * NCLASS + 32 + lane] = acc1;

    float av = acc0 * as[c0] + (act1 ? acc1 * as[c1] : 0.f);
    float dv = acc0 * ad[c0] + (act1 ? acc1 * ad[c1] : 0.f);
    #pragma unroll
    for (int o = 16; o > 0; o >>= 1) {
        av += __shfl_xor_sync(0xffffffffu, av, o);
        dv += __shfl_xor_sync(0xffffffffu, dv, o);
    }
    if (lane == 0) { g_asrc[n] = av; g_adst[n] = dv; }
}

// ---------------- GAT aggregate layer 1: warp per dst node ------------------
// No max subtraction (softmax shift-invariant; scores bounded small).
// Fuses normalize + bias + ReLU.
__global__ void gat1_kernel(const float* __restrict__ b1) {
    int lane = threadIdx.x & 31, w = threadIdx.x >> 5;
    int n = blockIdx.x * 8 + w;
    if (n >= N_NODES) return;
    int rs = g_rowptr[n], re = g_rowptr[n + 1];
    float adn = g_adst[n];
    float acc = 0.f, den = 0.f;

    for (int base = rs; base < re; base += 32) {
        int m = re - base;
        if (m > 32) m = 32;
        int s = 0;
        float ee = 0.f;
        if (lane < m) {
            s = g_srcs[base + lane];
            ee = __expf(lrelu(g_asrc[s] + adn));
        }
        den += ee;
        int j = 0;
        for (; j + 4 <= m; j += 4) {
            float e0 = __shfl_sync(0xffffffffu, ee, j);
            float e1 = __shfl_sync(0xffffffffu, ee, j + 1);
            float e2 = __shfl_sync(0xffffffffu, ee, j + 2);
            float e3 = __shfl_sync(0xffffffffu, ee, j + 3);
            int s0 = __shfl_sync(0xffffffffu, s, j);
            int s1 = __shfl_sync(0xffffffffu, s, j + 1);
            int s2 = __shfl_sync(0xffffffffu, s, j + 2);
            int s3 = __shfl_sync(0xffffffffu, s, j + 3);
            float h0 = g_h1[(size_t)s0 * NHID + lane];
            float h1 = g_h1[(size_t)s1 * NHID + lane];
            float h2 = g_h1[(size_t)s2 * NHID + lane];
            float h3 = g_h1[(size_t)s3 * NHID + lane];
            acc += e0 * h0 + e1 * h1 + e2 * h2 + e3 * h3;
        }
        for (; j < m; j++) {
            float ej = __shfl_sync(0xffffffffu, ee, j);
            int sj = __shfl_sync(0xffffffffu, s, j);
            acc += ej * g_h1[(size_t)sj * NHID + lane];
        }
    }
    // warp-sum den
    #pragma unroll
    for (int o = 16; o > 0; o >>= 1)
        den += __shfl_xor_sync(0xffffffffu, den, o);
    float v = acc / (den + 1e-16f) + b1[lane];
    g_x2[n * NHID + lane] = v > 0.f ? v : 0.f;
}

// ---------------- GAT aggregate layer 2 + log_softmax -----------------------
__global__ void gat2_kernel(const float* __restrict__ b2,
                            float* __restrict__ out) {
    int lane = threadIdx.x & 31, w = threadIdx.x >> 5;
    int n = blockIdx.x * 8 + w;
    if (n >= N_NODES) return;
    int rs = g_rowptr[n], re = g_rowptr[n + 1];
    float adn = g_adst[n];
    bool act1 = lane < 8;
    float acc0 = 0.f, acc1 = 0.f, den = 0.f;

    for (int base = rs; base < re; base += 32) {
        int m = re - base;
        if (m > 32) m = 32;
        int s = 0;
        float ee = 0.f;
        if (lane < m) {
            s = g_srcs[base + lane];
            ee = __expf(lrelu(g_asrc[s] + adn));
        }
        den += ee;
        int j = 0;
        for (; j + 2 <= m; j += 2) {
            float e0 = __shfl_sync(0xffffffffu, ee, j);
            float e1 = __shfl_sync(0xffffffffu, ee, j + 1);
            int s0 = __shfl_sync(0xffffffffu, s, j);
            int s1 = __shfl_sync(0xffffffffu, s, j + 1);
            const float* r0 = g_h2 + (size_t)s0 * NCLASS;
            const float* r1 = g_h2 + (size_t)s1 * NCLASS;
            float h00 = r0[lane];
            float h10 = r1[lane];
            float h01 = act1 ? r0[32 + lane] : 0.f;
            float h11 = act1 ? r1[32 + lane] : 0.f;
            acc0 += e0 * h00 + e1 * h10;
            acc1 += e0 * h01 + e1 * h11;
        }
        for (; j < m; j++) {
            float ej = __shfl_sync(0xffffffffu, ee, j);
            int sj = __shfl_sync(0xffffffffu, s, j);
            const float* r = g_h2 + (size_t)sj * NCLASS;
            acc0 += ej * r[lane];
            if (act1) acc1 += ej * r[32 + lane];
        }
    }
    #pragma unroll
    for (int o = 16; o > 0; o >>= 1)
        den += __shfl_xor_sync(0xffffffffu, den, o);
    float dn = den + 1e-16f;
    int c0 = lane;
    int c1 = act1 ? lane + 32 : 0;
    float v0 = acc0 / dn + b2[c0];
    float v1 = acc1 / dn + b2[c1];
    float vm = act1 ? fmaxf(v0, v1) : v0;
    #pragma unroll
    for (int o = 16; o > 0; o >>= 1)
        vm = fmaxf(vm, __shfl_xor_sync(0xffffffffu, vm, o));
    float ssum = expf(v0 - vm) + (act1 ? expf(v1 - vm) : 0.f);
    #pragma unroll
    for (int o = 16; o > 0; o >>= 1)
        ssum += __shfl_xor_sync(0xffffffffu, ssum, o);
    float lse = vm + logf(ssum);
    out[n * NCLASS + c0] = v0 - lse;
    if (act1) out[n * NCLASS + 32 + lane] = v1 - lse;
}

// ---------------- launch -----------------------------------------------------
extern "C" void kernel_launch(void* const* d_in, const int* in_sizes, int n_in,
                              void* d_out, int out_size) {
    const float* x   = (const float*)d_in[0];
    const int*   ei  = (const int*)d_in[1];
    const float* W1  = (const float*)d_in[2];
    const float* as1 = (const float*)d_in[3];
    const float* ad1 = (const float*)d_in[4];
    const float* b1  = (const float*)d_in[5];
    const float* W2  = (const float*)d_in[6];
    const float* as2 = (const float*)d_in[7];
    const float* ad2 = (const float*)d_in[8];
    const float* b2  = (const float*)d_in[9];
    const int* src = ei;
    const int* dst = ei + N_EDGES;
    float* out = (float*)d_out;

    const int TPB = 256;
    int node_grid = (N_NODES + TPB - 1) / TPB;
    int edge_grid = (N_EDGES + TPB - 1) / TPB;
    int warp8_grid = (N_NODES + 7) / 8;

    // CSR build (by destination)
    zero_deg_kernel<<<node_grid, TPB>>>();
    hist_kernel<<<edge_grid, TPB>>>(dst);
    scan_kernel<<<1, 1024>>>();
    scatter_kernel<<<edge_grid, TPB>>>(src, dst);

    // layer 1
    gemm1_kernel<<<N_NODES / 32, TPB>>>(x, W1, as1, ad1);
    gat1_kernel<<<warp8_grid, TPB>>>(b1);

    // layer 2
    gemm2_kernel<<<warp8_grid, TPB>>>(W2, as2, ad2);
    gat2_kernel<<<warp8_grid, TPB>>>(b2, out);
}

// round 4
// speedup vs baseline: 1.4188x; 1.4188x over previous
#include <cuda_runtime.h>
#include <cuda_bf16.h>
#include <math.h>
#include <limits.h>

#define N_NODES 100000
#define N_EDGES 1600000
#define NFEAT 128
#define NHID 32
#define NCLASS 40
#define NEG_SLOPE 0.2f

// ---------------- scratch (device globals; 16B-aligned for v4 atomics) -----
__device__ __align__(16) float g_h1[N_NODES * NHID];
__device__ __align__(16) float g_acc1[N_NODES * NHID];
__device__ __align__(16) float g_x2[N_NODES * NHID];
__device__ __align__(16) float g_h2[N_NODES * NCLASS];
__device__ __align__(16) float g_acc2[N_NODES * NCLASS];
__device__ float g_asrc[N_NODES];
__device__ float g_adst[N_NODES];
__device__ float g_denom1[N_NODES];
__device__ float g_denom2[N_NODES];

// ---------------- helpers ---------------------------------------------------
__device__ __forceinline__ float lrelu(float x) {
    return x > 0.f ? x : NEG_SLOPE * x;
}
__device__ __forceinline__ void red_add_v4(float* p, float4 v) {
    asm volatile("red.global.add.v4.f32 [%0], {%1,%2,%3,%4};"
                 :: "l"(p), "f"(v.x), "f"(v.y), "f"(v.z), "f"(v.w) : "memory");
}
__device__ __forceinline__ void red_add_f32(float* p, float v) {
    asm volatile("red.global.add.f32 [%0], %1;" :: "l"(p), "f"(v) : "memory");
}

// ---------------- init: zero everything in one pass -------------------------
// acc1 (3.2M) + acc2 (4M) + denom1/denom2 (0.1M each)
__global__ void init_kernel() {
    int i = blockIdx.x * blockDim.x + threadIdx.x;
    if (i < N_NODES * NHID)  g_acc1[i] = 0.f;
    if (i < N_NODES * NCLASS) g_acc2[i] = 0.f;
    if (i < N_NODES) { g_denom1[i] = 0.f; g_denom2[i] = 0.f; }
}

// ---------------- layer 1 GEMM: h1 = x @ W1, + alpha_src/dst ---------------
__global__ void gemm1_kernel(const float* __restrict__ x,
                             const float* __restrict__ W1,
                             const float* __restrict__ a_src,
                             const float* __restrict__ a_dst) {
    __shared__ float Wsh[NFEAT * NHID];
    __shared__ float xsh[32][NFEAT];
    __shared__ float as[NHID], ad[NHID];
    int tid = threadIdx.x;
    int base = blockIdx.x * 32;

    for (int i = tid; i < NFEAT * NHID; i += 256) Wsh[i] = W1[i];
    if (tid < NHID) { as[tid] = a_src[tid]; ad[tid] = a_dst[tid]; }
    for (int i = tid; i < 32 * NFEAT; i += 256) {
        int r = i >> 7, cc = i & 127;
        xsh[r][cc] = x[(size_t)(base + r) * NFEAT + cc];
    }
    __syncthreads();

    int c = tid & 31, rr = tid >> 5;
    float acc[4] = {0.f, 0.f, 0.f, 0.f};
    #pragma unroll 8
    for (int k = 0; k < NFEAT; k++) {
        float wk = Wsh[k * NHID + c];
        acc[0] += xsh[rr     ][k] * wk;
        acc[1] += xsh[rr +  8][k] * wk;
        acc[2] += xsh[rr + 16][k] * wk;
        acc[3] += xsh[rr + 24][k] * wk;
    }
    #pragma unroll
    for (int j = 0; j < 4; j++) {
        int n = base + rr + 8 * j;
        g_h1[n * NHID + c] = acc[j];
        float av = acc[j] * as[c];
        float dv = acc[j] * ad[c];
        #pragma unroll
        for (int o = 16; o > 0; o >>= 1) {
            av += __shfl_xor_sync(0xffffffffu, av, o);
            dv += __shfl_xor_sync(0xffffffffu, dv, o);
        }
        if (c == 0) { g_asrc[n] = av; g_adst[n] = dv; }
    }
}

// ---------------- layer 2 GEMM ---------------------------------------------
__global__ void gemm2_kernel(const float* __restrict__ W2,
                             const float* __restrict__ a_src,
                             const float* __restrict__ a_dst) {
    __shared__ float Wsh[NHID * NCLASS];
    __shared__ float as[NCLASS], ad[NCLASS];
    int tid = threadIdx.x;
    for (int i = tid; i < NHID * NCLASS; i += 256) Wsh[i] = W2[i];
    if (tid < NCLASS) { as[tid] = a_src[tid]; ad[tid] = a_dst[tid]; }
    __syncthreads();

    int lane = tid & 31, w = tid >> 5;
    int n = blockIdx.x * 8 + w;
    float hval = g_x2[n * NHID + lane];
    bool act1 = lane < 8;
    int c0 = lane;
    int c1 = act1 ? lane + 32 : 0;
    float acc0 = 0.f, acc1 = 0.f;
    #pragma unroll
    for (int k = 0; k < NHID; k++) {
        float hk = __shfl_sync(0xffffffffu, hval, k);
        acc0 += hk * Wsh[k * NCLASS + c0];
        acc1 += hk * Wsh[k * NCLASS + c1];
    }
    g_h2[n * NCLASS + c0] = acc0;
    if (act1) g_h2[n * NCLASS + 32 + lane] = acc1;

    float av = acc0 * as[c0] + (act1 ? acc1 * as[c1] : 0.f);
    float dv = acc0 * ad[c0] + (act1 ? acc1 * ad[c1] : 0.f);
    #pragma unroll
    for (int o = 16; o > 0; o >>= 1) {
        av += __shfl_xor_sync(0xffffffffu, av, o);
        dv += __shfl_xor_sync(0xffffffffu, dv, o);
    }
    if (lane == 0) { g_asrc[n] = av; g_adst[n] = dv; }
}

// ---------------- edge pass: fused exp + denom + v4 scatter ----------------
// No max subtraction (softmax shift-invariant; glorot-scaled scores small).
// Flat mapping: one thread per float4 chunk. VPE = C/4 threads per edge.
template <int C>
__global__ void edge_accum_kernel(const int* __restrict__ src,
                                  const int* __restrict__ dst) {
    constexpr int VPE = C / 4;  // 8 (C=32) or 10 (C=40)
    int t = blockIdx.x * blockDim.x + threadIdx.x;
    int e = t / VPE;
    int v = t - e * VPE;
    if (e >= N_EDGES) return;
    const float* __restrict__ h   = (C == NHID) ? g_h1    : g_h2;
    float* __restrict__       ac  = (C == NHID) ? g_acc1  : g_acc2;
    float* __restrict__       dnm = (C == NHID) ? g_denom1 : g_denom2;
    int s = __ldg(&src[e]), d = __ldg(&dst[e]);
    float ee = __expf(lrelu(g_asrc[s] + g_adst[d]));
    if (v == 0) red_add_f32(&dnm[d], ee);
    float4 hv = __ldg(reinterpret_cast<const float4*>(h + (size_t)s * C) + v);
    hv.x *= ee; hv.y *= ee; hv.z *= ee; hv.w *= ee;
    red_add_v4(ac + (size_t)d * C + 4 * v, hv);
}

// ---------------- finalize layer 1 -----------------------------------------
__global__ void finalize1_kernel(const float* __restrict__ b1) {
    int i = blockIdx.x * blockDim.x + threadIdx.x;
    if (i >= N_NODES * NHID) return;
    int n = i >> 5, c = i & 31;
    float v = g_acc1[i] / (g_denom1[n] + 1e-16f) + b1[c];
    g_x2[i] = v > 0.f ? v : 0.f;
}

// ---------------- finalize layer 2: log_softmax ----------------------------
__global__ void finalize2_kernel(const float* __restrict__ b2,
                                 float* __restrict__ out) {
    int lane = threadIdx.x & 31, w = threadIdx.x >> 5;
    int n = blockIdx.x * 8 + w;
    float dn = g_denom2[n] + 1e-16f;
    bool act1 = lane < 8;
    int c0 = lane;
    int c1 = act1 ? lane + 32 : 0;
    float v0 = g_acc2[n * NCLASS + c0] / dn + b2[c0];
    float v1 = g_acc2[n * NCLASS + c1] / dn + b2[c1];
    float vm = act1 ? fmaxf(v0, v1) : v0;
    #pragma unroll
    for (int o = 16; o > 0; o >>= 1)
        vm = fmaxf(vm, __shfl_xor_sync(0xffffffffu, vm, o));
    float s = expf(v0 - vm) + (act1 ? expf(v1 - vm) : 0.f);
    #pragma unroll
    for (int o = 16; o > 0; o >>= 1)
        s += __shfl_xor_sync(0xffffffffu, s, o);
    float lse = vm + logf(s);
    out[n * NCLASS + c0] = v0 - lse;
    if (act1) out[n * NCLASS + 32 + lane] = v1 - lse;
}

// ---------------- launch ----------------------------------------------------
extern "C" void kernel_launch(void* const* d_in, const int* in_sizes, int n_in,
                              void* d_out, int out_size) {
    const float* x   = (const float*)d_in[0];
    const int*   ei  = (const int*)d_in[1];
    const float* W1  = (const float*)d_in[2];
    const float* as1 = (const float*)d_in[3];
    const float* ad1 = (const float*)d_in[4];
    const float* b1  = (const float*)d_in[5];
    const float* W2  = (const float*)d_in[6];
    const float* as2 = (const float*)d_in[7];
    const float* ad2 = (const float*)d_in[8];
    const float* b2  = (const float*)d_in[9];
    const int* src = ei;
    const int* dst = ei + N_EDGES;
    float* out = (float*)d_out;

    const int TPB = 256;
    int init_grid  = (N_NODES * NCLASS + TPB - 1) / TPB;  // covers all arrays
    int fin1_grid  = (N_NODES * NHID + TPB - 1) / TPB;
    int eacc1_grid = (N_EDGES * (NHID / 4) + TPB - 1) / TPB;
    int eacc2_grid = (N_EDGES * (NCLASS / 4) + TPB - 1) / TPB;
    int warp8_grid = (N_NODES + 7) / 8;

    init_kernel<<<init_grid, TPB>>>();

    // ---- layer 1 ----
    gemm1_kernel<<<N_NODES / 32, TPB>>>(x, W1, as1, ad1);
    edge_accum_kernel<NHID><<<eacc1_grid, TPB>>>(src, dst);
    finalize1_kernel<<<fin1_grid, TPB>>>(b1);

    // ---- layer 2 ----
    gemm2_kernel<<<warp8_grid, TPB>>>(W2, as2, ad2);
    edge_accum_kernel<NCLASS><<<eacc2_grid, TPB>>>(src, dst);
    finalize2_kernel<<<warp8_grid, TPB>>>(b2, out);
}

// round 5
// speedup vs baseline: 1.6013x; 1.1287x over previous
#include <cuda_runtime.h>
#include <cuda_bf16.h>
#include <math.h>
#include <limits.h>

#define N_NODES 100000
#define N_EDGES 1600000
#define NFEAT 128
#define NHID 32
#define NCLASS 40
#define NEG_SLOPE 0.2f

// ---------------- scratch ----------------------------------------------------
__device__ __align__(16) float g_h1[N_NODES * NHID];    // layer1 node features
__device__ __align__(16) float g_acc1[N_NODES * NHID];  // layer1 message accum
__device__ __align__(16) float g_x2[N_NODES * NHID];    // layer1 output
__device__ __align__(16) float g_acc2[N_NODES * NHID];  // layer2 aggregated x2
__device__ float g_asrc[N_NODES];
__device__ float g_adst[N_NODES];
__device__ float g_denom1[N_NODES];
__device__ float g_denom2[N_NODES];
__device__ float g_was2[NHID];   // W2 @ a_src2
__device__ float g_wad2[NHID];   // W2 @ a_dst2

// ---------------- helpers ---------------------------------------------------
__device__ __forceinline__ float lrelu(float x) {
    return x > 0.f ? x : NEG_SLOPE * x;
}
__device__ __forceinline__ void red_add_v4(float* p, float4 v) {
    asm volatile("red.global.add.v4.f32 [%0], {%1,%2,%3,%4};"
                 :: "l"(p), "f"(v.x), "f"(v.y), "f"(v.z), "f"(v.w) : "memory");
}
__device__ __forceinline__ void red_add_f32(float* p, float v) {
    asm volatile("red.global.add.f32 [%0], %1;" :: "l"(p), "f"(v) : "memory");
}

// ---------------- prep: w_as2 = W2 @ a_src2, w_ad2 = W2 @ a_dst2 ------------
__global__ void prep2_kernel(const float* __restrict__ W2,
                             const float* __restrict__ as2,
                             const float* __restrict__ ad2) {
    int t = threadIdx.x;
    int k = t & 31;
    const float* a = (t < 32) ? as2 : ad2;
    float s = 0.f;
    #pragma unroll
    for (int c = 0; c < NCLASS; c++) s += W2[k * NCLASS + c] * a[c];
    if (t < 32) g_was2[k] = s;
    else        g_wad2[k] = s;
}

// ---------------- layer 1 GEMM: h1 = x @ W1, + alpha_src/dst + zero acc1 ----
__global__ void gemm1_kernel(const float* __restrict__ x,
                             const float* __restrict__ W1,
                             const float* __restrict__ a_src,
                             const float* __restrict__ a_dst) {
    __shared__ float Wsh[NFEAT * NHID];
    __shared__ float xsh[32][NFEAT];
    __shared__ float as[NHID], ad[NHID];
    int tid = threadIdx.x;
    int base = blockIdx.x * 32;

    for (int i = tid; i < NFEAT * NHID; i += 256) Wsh[i] = W1[i];
    if (tid < NHID) { as[tid] = a_src[tid]; ad[tid] = a_dst[tid]; }
    for (int i = tid; i < 32 * NFEAT; i += 256) {
        int r = i >> 7, cc = i & 127;
        xsh[r][cc] = x[(size_t)(base + r) * NFEAT + cc];
    }
    __syncthreads();

    int c = tid & 31, rr = tid >> 5;
    float acc[4] = {0.f, 0.f, 0.f, 0.f};
    #pragma unroll 8
    for (int k = 0; k < NFEAT; k++) {
        float wk = Wsh[k * NHID + c];
        acc[0] += xsh[rr     ][k] * wk;
        acc[1] += xsh[rr +  8][k] * wk;
        acc[2] += xsh[rr + 16][k] * wk;
        acc[3] += xsh[rr + 24][k] * wk;
    }
    #pragma unroll
    for (int j = 0; j < 4; j++) {
        int n = base + rr + 8 * j;
        g_h1[n * NHID + c] = acc[j];
        g_acc1[n * NHID + c] = 0.f;           // zero accumulator inline
        float av = acc[j] * as[c];
        float dv = acc[j] * ad[c];
        #pragma unroll
        for (int o = 16; o > 0; o >>= 1) {
            av += __shfl_xor_sync(0xffffffffu, av, o);
            dv += __shfl_xor_sync(0xffffffffu, dv, o);
        }
        if (c == 0) {
            g_asrc[n] = av; g_adst[n] = dv; g_denom1[n] = 0.f;
        }
    }
}

// ---------------- edge pass: fused exp + denom + v4 scatter ----------------
// C=32 both layers. Flat mapping: thread per float4 chunk (VPE=8, warp=4 edges).
template <int LAYER>
__global__ void edge_accum_kernel(const int* __restrict__ src,
                                  const int* __restrict__ dst) {
    int t = blockIdx.x * blockDim.x + threadIdx.x;
    int e = t >> 3;
    int v = t & 7;
    if (e >= N_EDGES) return;
    const float* __restrict__ h   = (LAYER == 1) ? g_h1     : g_x2;
    float* __restrict__       ac  = (LAYER == 1) ? g_acc1   : g_acc2;
    float* __restrict__       dnm = (LAYER == 1) ? g_denom1 : g_denom2;
    int s = __ldg(&src[e]), d = __ldg(&dst[e]);
    float ee = __expf(lrelu(g_asrc[s] + g_adst[d]));
    if (v == 0) red_add_f32(&dnm[d], ee);
    float4 hv = __ldg(reinterpret_cast<const float4*>(h + (size_t)s * NHID) + v);
    hv.x *= ee; hv.y *= ee; hv.z *= ee; hv.w *= ee;
    red_add_v4(ac + (size_t)d * NHID + 4 * v, hv);
}

// ---------------- finalize layer 1: x2 = relu(...); layer-2 scores; zero acc2
__global__ void finalize1_kernel(const float* __restrict__ b1) {
    int lane = threadIdx.x & 31, w = threadIdx.x >> 5;
    int n = blockIdx.x * 8 + w;
    if (n >= N_NODES) return;
    int i = n * NHID + lane;
    float v = g_acc1[i] / (g_denom1[n] + 1e-16f) + __ldg(&b1[lane]);
    v = v > 0.f ? v : 0.f;
    g_x2[i] = v;
    g_acc2[i] = 0.f;                          // zero layer-2 accumulator
    float av = v * g_was2[lane];
    float dv = v * g_wad2[lane];
    #pragma unroll
    for (int o = 16; o > 0; o >>= 1) {
        av += __shfl_xor_sync(0xffffffffu, av, o);
        dv += __shfl_xor_sync(0xffffffffu, dv, o);
    }
    if (lane == 0) {
        g_asrc[n] = av; g_adst[n] = dv; g_denom2[n] = 0.f;
    }
}

// ---------------- finalize layer 2: matvec W2 + bias + log_softmax ----------
__global__ void finalize2_kernel(const float* __restrict__ W2,
                                 const float* __restrict__ b2,
                                 float* __restrict__ out) {
    __shared__ float Wsh[NHID * NCLASS];
    __shared__ float bsh[NCLASS];
    int tid = threadIdx.x;
    for (int i = tid; i < NHID * NCLASS; i += 256) Wsh[i] = W2[i];
    if (tid < NCLASS) bsh[tid] = b2[tid];
    __syncthreads();

    int lane = tid & 31, w = tid >> 5;
    int n = blockIdx.x * 8 + w;
    if (n >= N_NODES) return;
    float a = g_acc2[n * NHID + lane] / (g_denom2[n] + 1e-16f);
    bool act1 = lane < 8;
    int c0 = lane;
    int c1 = act1 ? lane + 32 : 0;
    float y0 = 0.f, y1 = 0.f;
    #pragma unroll
    for (int k = 0; k < NHID; k++) {
        float ak = __shfl_sync(0xffffffffu, a, k);
        y0 += ak * Wsh[k * NCLASS + c0];
        y1 += ak * Wsh[k * NCLASS + c1];
    }
    y0 += bsh[c0];
    y1 += bsh[c1];
    float vm = act1 ? fmaxf(y0, y1) : y0;
    #pragma unroll
    for (int o = 16; o > 0; o >>= 1)
        vm = fmaxf(vm, __shfl_xor_sync(0xffffffffu, vm, o));
    float ssum = expf(y0 - vm) + (act1 ? expf(y1 - vm) : 0.f);
    #pragma unroll
    for (int o = 16; o > 0; o >>= 1)
        ssum += __shfl_xor_sync(0xffffffffu, ssum, o);
    float lse = vm + logf(ssum);
    out[n * NCLASS + c0] = y0 - lse;
    if (act1) out[n * NCLASS + 32 + lane] = y1 - lse;
}

// ---------------- launch ----------------------------------------------------
extern "C" void kernel_launch(void* const* d_in, const int* in_sizes, int n_in,
                              void* d_out, int out_size) {
    const float* x   = (const float*)d_in[0];
    const int*   ei  = (const int*)d_in[1];
    const float* W1  = (const float*)d_in[2];
    const float* as1 = (const float*)d_in[3];
    const float* ad1 = (const float*)d_in[4];
    const float* b1  = (const float*)d_in[5];
    const float* W2  = (const float*)d_in[6];
    const float* as2 = (const float*)d_in[7];
    const float* ad2 = (const float*)d_in[8];
    const float* b2  = (const float*)d_in[9];
    const int* src = ei;
    const int* dst = ei + N_EDGES;
    float* out = (float*)d_out;

    const int TPB = 256;
    int eacc_grid  = (N_EDGES * 8 + TPB - 1) / TPB;
    int warp8_grid = (N_NODES + 7) / 8;

    prep2_kernel<<<1, 64>>>(W2, as2, ad2);

    // ---- layer 1 ----
    gemm1_kernel<<<N_NODES / 32, TPB>>>(x, W1, as1, ad1);
    edge_accum_kernel<1><<<eacc_grid, TPB>>>(src, dst);
    finalize1_kernel<<<warp8_grid, TPB>>>(b1);

    // ---- layer 2 ----
    edge_accum_kernel<2><<<eacc_grid, TPB>>>(src, dst);
    finalize2_kernel<<<warp8_grid, TPB>>>(W2, b2, out);
}

// round 6
// speedup vs baseline: 1.7381x; 1.0854x over previous
#include <cuda_runtime.h>
#include <cuda_bf16.h>
#include <math.h>
#include <limits.h>

#define N_NODES 100000
#define N_EDGES 1600000
#define NFEAT 128
#define NHID 32
#define NCLASS 40
#define NEG_SLOPE 0.2f

// ---------------- scratch ----------------------------------------------------
__device__ __align__(16) float g_h1[N_NODES * NHID];    // layer1 node features
__device__ __align__(16) float g_acc1[N_NODES * NHID];  // layer1 message accum
__device__ __align__(16) float g_x2[N_NODES * NHID];    // layer1 output
__device__ __align__(16) float g_acc2[N_NODES * NHID];  // layer2 aggregated x2
__device__ float g_asrc[N_NODES];
__device__ float g_adst[N_NODES];
__device__ float g_denom1[N_NODES];
__device__ float g_denom2[N_NODES];

// ---------------- helpers ---------------------------------------------------
__device__ __forceinline__ float lrelu(float x) {
    return x > 0.f ? x : NEG_SLOPE * x;
}
__device__ __forceinline__ void red_add_v4(float* p, float4 v) {
    asm volatile("red.global.add.v4.f32 [%0], {%1,%2,%3,%4};"
                 :: "l"(p), "f"(v.x), "f"(v.y), "f"(v.z), "f"(v.w) : "memory");
}
__device__ __forceinline__ void red_add_f32(float* p, float v) {
    asm volatile("red.global.add.f32 [%0], %1;" :: "l"(p), "f"(v) : "memory");
}

// ---------------- layer 1 GEMM: h1 = x @ W1, + alpha_src/dst + zero acc1 ----
__global__ void gemm1_kernel(const float* __restrict__ x,
                             const float* __restrict__ W1,
                             const float* __restrict__ a_src,
                             const float* __restrict__ a_dst) {
    __shared__ float Wsh[NFEAT * NHID];
    __shared__ float xsh[32][NFEAT];
    __shared__ float as[NHID], ad[NHID];
    int tid = threadIdx.x;
    int base = blockIdx.x * 32;

    // vectorized loads
    const float4* W4 = reinterpret_cast<const float4*>(W1);
    float4* Wsh4 = reinterpret_cast<float4*>(Wsh);
    for (int i = tid; i < NFEAT * NHID / 4; i += 256) Wsh4[i] = W4[i];
    if (tid < NHID) { as[tid] = a_src[tid]; ad[tid] = a_dst[tid]; }
    const float4* x4 = reinterpret_cast<const float4*>(x);
    for (int i = tid; i < 32 * NFEAT / 4; i += 256) {
        int r = i >> 5, cc = i & 31;  // 32 float4 per row
        reinterpret_cast<float4*>(&xsh[r][0])[cc] =
            x4[(size_t)(base + r) * (NFEAT / 4) + cc];
    }
    __syncthreads();

    int c = tid & 31, rr = tid >> 5;
    float acc[4] = {0.f, 0.f, 0.f, 0.f};
    #pragma unroll 8
    for (int k = 0; k < NFEAT; k++) {
        float wk = Wsh[k * NHID + c];
        acc[0] += xsh[rr     ][k] * wk;
        acc[1] += xsh[rr +  8][k] * wk;
        acc[2] += xsh[rr + 16][k] * wk;
        acc[3] += xsh[rr + 24][k] * wk;
    }
    #pragma unroll
    for (int j = 0; j < 4; j++) {
        int n = base + rr + 8 * j;
        g_h1[n * NHID + c] = acc[j];
        g_acc1[n * NHID + c] = 0.f;
        float av = acc[j] * as[c];
        float dv = acc[j] * ad[c];
        #pragma unroll
        for (int o = 16; o > 0; o >>= 1) {
            av += __shfl_xor_sync(0xffffffffu, av, o);
            dv += __shfl_xor_sync(0xffffffffu, dv, o);
        }
        if (c == 0) {
            g_asrc[n] = av; g_adst[n] = dv; g_denom1[n] = 0.f;
        }
    }
}

// ---------------- edge pass: fused exp + denom + v4 scatter ----------------
template <int LAYER>
__global__ void edge_accum_kernel(const int* __restrict__ src,
                                  const int* __restrict__ dst) {
    int t = blockIdx.x * blockDim.x + threadIdx.x;
    int e = t >> 3;
    int v = t & 7;
    if (e >= N_EDGES) return;
    const float* __restrict__ h   = (LAYER == 1) ? g_h1     : g_x2;
    float* __restrict__       ac  = (LAYER == 1) ? g_acc1   : g_acc2;
    float* __restrict__       dnm = (LAYER == 1) ? g_denom1 : g_denom2;
    int s = __ldg(&src[e]), d = __ldg(&dst[e]);
    float ee = __expf(lrelu(g_asrc[s] + g_adst[d]));
    if (v == 0) red_add_f32(&dnm[d], ee);
    float4 hv = __ldg(reinterpret_cast<const float4*>(h + (size_t)s * NHID) + v);
    hv.x *= ee; hv.y *= ee; hv.z *= ee; hv.w *= ee;
    red_add_v4(ac + (size_t)d * NHID + 4 * v, hv);
}

// ---------------- finalize layer 1: x2=relu(.), layer-2 scores, zero acc2 ---
// 8 threads per node, float4 per thread; 32 nodes per 256-thread block.
// Also computes was2/wad2 = W2 @ a_{src,dst}2 per block (replaces prep kernel).
__global__ void finalize1_kernel(const float* __restrict__ b1,
                                 const float* __restrict__ W2,
                                 const float* __restrict__ as2,
                                 const float* __restrict__ ad2) {
    __shared__ float was[NHID], wad[NHID], b1s[NHID];
    int tid = threadIdx.x;
    if (tid < 64) {
        int k = tid & 31;
        const float* a = (tid < 32) ? as2 : ad2;
        float s = 0.f;
        #pragma unroll
        for (int c = 0; c < NCLASS; c++) s += W2[k * NCLASS + c] * a[c];
        if (tid < 32) was[k] = s; else wad[k] = s;
    } else if (tid < 96) {
        b1s[tid - 64] = b1[tid - 64];
    }
    __syncthreads();

    int g = tid >> 3, v = tid & 7;
    int n = blockIdx.x * 32 + g;
    if (n >= N_NODES) return;
    float inv = 1.f / (g_denom1[n] + 1e-16f);
    float4 a = *reinterpret_cast<const float4*>(g_acc1 + (size_t)n * NHID + 4 * v);
    float4 bb = *reinterpret_cast<const float4*>(b1s + 4 * v);
    float4 r;
    r.x = fmaxf(a.x * inv + bb.x, 0.f);
    r.y = fmaxf(a.y * inv + bb.y, 0.f);
    r.z = fmaxf(a.z * inv + bb.z, 0.f);
    r.w = fmaxf(a.w * inv + bb.w, 0.f);
    *reinterpret_cast<float4*>(g_x2 + (size_t)n * NHID + 4 * v) = r;
    *reinterpret_cast<float4*>(g_acc2 + (size_t)n * NHID + 4 * v) =
        make_float4(0.f, 0.f, 0.f, 0.f);

    float4 wa = *reinterpret_cast<const float4*>(was + 4 * v);
    float4 wd = *reinterpret_cast<const float4*>(wad + 4 * v);
    float av = r.x * wa.x + r.y * wa.y + r.z * wa.z + r.w * wa.w;
    float dv = r.x * wd.x + r.y * wd.y + r.z * wd.z + r.w * wd.w;
    #pragma unroll
    for (int o = 4; o > 0; o >>= 1) {
        av += __shfl_xor_sync(0xffffffffu, av, o);
        dv += __shfl_xor_sync(0xffffffffu, dv, o);
    }
    if (v == 0) {
        g_asrc[n] = av; g_adst[n] = dv; g_denom2[n] = 0.f;
    }
}

// ---------------- finalize layer 2: matvec W2 + bias + log_softmax ----------
__global__ void finalize2_kernel(const float* __restrict__ W2,
                                 const float* __restrict__ b2,
                                 float* __restrict__ out) {
    __shared__ float Wsh[NHID * NCLASS];
    __shared__ float bsh[NCLASS];
    int tid = threadIdx.x;
    for (int i = tid; i < NHID * NCLASS; i += 256) Wsh[i] = W2[i];
    if (tid < NCLASS) bsh[tid] = b2[tid];
    __syncthreads();

    int lane = tid & 31, w = tid >> 5;
    int n = blockIdx.x * 8 + w;
    if (n >= N_NODES) return;
    float a = g_acc2[(size_t)n * NHID + lane] / (g_denom2[n] + 1e-16f);
    bool act1 = lane < 8;
    int c0 = lane;
    int c1 = act1 ? lane + 32 : 0;
    float y0 = 0.f, y1 = 0.f;
    #pragma unroll
    for (int k = 0; k < NHID; k++) {
        float ak = __shfl_sync(0xffffffffu, a, k);
        y0 += ak * Wsh[k * NCLASS + c0];
        y1 += ak * Wsh[k * NCLASS + c1];
    }
    y0 += bsh[c0];
    y1 += bsh[c1];
    float vm = act1 ? fmaxf(y0, y1) : y0;
    #pragma unroll
    for (int o = 16; o > 0; o >>= 1)
        vm = fmaxf(vm, __shfl_xor_sync(0xffffffffu, vm, o));
    float ssum = expf(y0 - vm) + (act1 ? expf(y1 - vm) : 0.f);
    #pragma unroll
    for (int o = 16; o > 0; o >>= 1)
        ssum += __shfl_xor_sync(0xffffffffu, ssum, o);
    float lse = vm + logf(ssum);
    out[n * NCLASS + c0] = y0 - lse;
    if (act1) out[n * NCLASS + 32 + lane] = y1 - lse;
}

// ---------------- launch ----------------------------------------------------
extern "C" void kernel_launch(void* const* d_in, const int* in_sizes, int n_in,
                              void* d_out, int out_size) {
    const float* x   = (const float*)d_in[0];
    const int*   ei  = (const int*)d_in[1];
    const float* W1  = (const float*)d_in[2];
    const float* as1 = (const float*)d_in[3];
    const float* ad1 = (const float*)d_in[4];
    const float* b1  = (const float*)d_in[5];
    const float* W2  = (const float*)d_in[6];
    const float* as2 = (const float*)d_in[7];
    const float* ad2 = (const float*)d_in[8];
    const float* b2  = (const float*)d_in[9];
    const int* src = ei;
    const int* dst = ei + N_EDGES;
    float* out = (float*)d_out;

    const int TPB = 256;
    int eacc_grid  = (N_EDGES * 8 + TPB - 1) / TPB;
    int fin1_grid  = (N_NODES + 31) / 32;
    int warp8_grid = (N_NODES + 7) / 8;

    // ---- layer 1 ----
    gemm1_kernel<<<N_NODES / 32, TPB>>>(x, W1, as1, ad1);
    edge_accum_kernel<1><<<eacc_grid, TPB>>>(src, dst);
    finalize1_kernel<<<fin1_grid, TPB>>>(b1, W2, as2, ad2);

    // ---- layer 2 ----
    edge_accum_kernel<2><<<eacc_grid, TPB>>>(src, dst);
    finalize2_kernel<<<warp8_grid, TPB>>>(W2, b2, out);
}

// round 8
// speedup vs baseline: 1.8530x; 1.0661x over previous
#include <cuda_runtime.h>
#include <cuda_bf16.h>
#include <math.h>
#include <limits.h>

#define N_NODES 100000
#define N_EDGES 1600000
#define NFEAT 128
#define NHID 32
#define NCLASS 40
#define NEG_SLOPE 0.2f

// ---------------- scratch ----------------------------------------------------
__device__ __align__(16) float g_h1[N_NODES * NHID];
__device__ __align__(16) float g_acc1[N_NODES * NHID];
__device__ __align__(16) float g_x2[N_NODES * NHID];
__device__ __align__(16) float g_acc2[N_NODES * NHID];
__device__ float g_asrc[N_NODES];
__device__ float g_adst[N_NODES];
__device__ float g_denom1[N_NODES];
__device__ float g_denom2[N_NODES];

// ---------------- helpers ---------------------------------------------------
__device__ __forceinline__ float lrelu(float x) {
    return x > 0.f ? x : NEG_SLOPE * x;
}
__device__ __forceinline__ void red_add_v4(float* p, float4 v) {
    asm volatile("red.global.add.v4.f32 [%0], {%1,%2,%3,%4};"
                 :: "l"(p), "f"(v.x), "f"(v.y), "f"(v.z), "f"(v.w) : "memory");
}
__device__ __forceinline__ void red_add_f32(float* p, float v) {
    asm volatile("red.global.add.f32 [%0], %1;" :: "l"(p), "f"(v) : "memory");
}

// ---------------- layer 1 GEMM: 64 nodes/block, h1 = x @ W1 + scores --------
// smem = 16KB (W) + 32KB (x tile) = exactly 48KB static.
__global__ void gemm1_kernel(const float* __restrict__ x,
                             const float* __restrict__ W1,
                             const float* __restrict__ a_src,
                             const float* __restrict__ a_dst) {
    __shared__ float Wsh[NFEAT * NHID];          // 16 KB
    __shared__ float xsh[64][NFEAT];             // 32 KB
    int tid = threadIdx.x;
    int base = blockIdx.x * 64;

    const float4* W4 = reinterpret_cast<const float4*>(W1);
    float4* Wsh4 = reinterpret_cast<float4*>(Wsh);
    #pragma unroll
    for (int i = tid; i < NFEAT * NHID / 4; i += 256) Wsh4[i] = W4[i];
    const float4* x4 = reinterpret_cast<const float4*>(x);
    #pragma unroll
    for (int i = tid; i < 64 * NFEAT / 4; i += 256) {
        int r = i >> 5, cc = i & 31;             // 32 float4 per row
        if (base + r < N_NODES)
            reinterpret_cast<float4*>(&xsh[r][0])[cc] =
                x4[(size_t)(base + r) * (NFEAT / 4) + cc];
    }
    __syncthreads();

    int c = tid & 31, rr = tid >> 5;             // channel, row subgroup 0..7
    float asc = __ldg(&a_src[c]);                // per-thread scalar (L1-resident)
    float adc = __ldg(&a_dst[c]);
    float acc[8];
    #pragma unroll
    for (int j = 0; j < 8; j++) acc[j] = 0.f;
    #pragma unroll 4
    for (int k = 0; k < NFEAT; k++) {
        float wk = Wsh[k * NHID + c];
        #pragma unroll
        for (int j = 0; j < 8; j++)
            acc[j] += xsh[rr + 8 * j][k] * wk;
    }
    #pragma unroll
    for (int j = 0; j < 8; j++) {
        int n = base + rr + 8 * j;
        if (n >= N_NODES) continue;              // uniform per-warp branch
        g_h1[(size_t)n * NHID + c] = acc[j];
        g_acc1[(size_t)n * NHID + c] = 0.f;
        float av = acc[j] * asc;
        float dv = acc[j] * adc;
        #pragma unroll
        for (int o = 16; o > 0; o >>= 1) {
            av += __shfl_xor_sync(0xffffffffu, av, o);
            dv += __shfl_xor_sync(0xffffffffu, dv, o);
        }
        if (c == 0) {
            g_asrc[n] = av; g_adst[n] = dv; g_denom1[n] = 0.f;
        }
    }
}

// ---------------- edge pass: 2 edges per thread, fused exp + v4 scatter -----
template <int LAYER>
__global__ void edge_accum_kernel(const int* __restrict__ src,
                                  const int* __restrict__ dst) {
    int t = blockIdx.x * blockDim.x + threadIdx.x;
    int v = t & 7;
    int e0 = (t >> 3) * 2;
    if (e0 >= N_EDGES) return;
    int e1 = e0 + 1;
    const float* __restrict__ h   = (LAYER == 1) ? g_h1     : g_x2;
    float* __restrict__       ac  = (LAYER == 1) ? g_acc1   : g_acc2;
    float* __restrict__       dnm = (LAYER == 1) ? g_denom1 : g_denom2;

    // batched independent loads (2 chains in flight)
    int s0 = __ldg(&src[e0]), s1 = __ldg(&src[e1]);
    int d0 = __ldg(&dst[e0]), d1 = __ldg(&dst[e1]);
    float as0 = __ldg(&g_asrc[s0]), as1 = __ldg(&g_asrc[s1]);
    float ad0 = __ldg(&g_adst[d0]), ad1 = __ldg(&g_adst[d1]);
    float4 h0 = __ldg(reinterpret_cast<const float4*>(h + (size_t)s0 * NHID) + v);
    float4 h1 = __ldg(reinterpret_cast<const float4*>(h + (size_t)s1 * NHID) + v);
    float ee0 = __expf(lrelu(as0 + ad0));
    float ee1 = __expf(lrelu(as1 + ad1));
    if (v == 0) {
        red_add_f32(&dnm[d0], ee0);
        red_add_f32(&dnm[d1], ee1);
    }
    h0.x *= ee0; h0.y *= ee0; h0.z *= ee0; h0.w *= ee0;
    h1.x *= ee1; h1.y *= ee1; h1.z *= ee1; h1.w *= ee1;
    red_add_v4(ac + (size_t)d0 * NHID + 4 * v, h0);
    red_add_v4(ac + (size_t)d1 * NHID + 4 * v, h1);
}

// ---------------- finalize layer 1 ------------------------------------------
__global__ void finalize1_kernel(const float* __restrict__ b1,
                                 const float* __restrict__ W2,
                                 const float* __restrict__ as2,
                                 const float* __restrict__ ad2) {
    __shared__ float was[NHID], wad[NHID], b1s[NHID];
    int tid = threadIdx.x;
    if (tid < 64) {
        int k = tid & 31;
        const float* a = (tid < 32) ? as2 : ad2;
        float s = 0.f;
        #pragma unroll
        for (int c = 0; c < NCLASS; c++) s += W2[k * NCLASS + c] * a[c];
        if (tid < 32) was[k] = s; else wad[k] = s;
    } else if (tid < 96) {
        b1s[tid - 64] = b1[tid - 64];
    }
    __syncthreads();

    int g = tid >> 3, v = tid & 7;
    int n = blockIdx.x * 32 + g;
    if (n >= N_NODES) return;
    float inv = 1.f / (g_denom1[n] + 1e-16f);
    float4 a = *reinterpret_cast<const float4*>(g_acc1 + (size_t)n * NHID + 4 * v);
    float4 bb = *reinterpret_cast<const float4*>(b1s + 4 * v);
    float4 r;
    r.x = fmaxf(a.x * inv + bb.x, 0.f);
    r.y = fmaxf(a.y * inv + bb.y, 0.f);
    r.z = fmaxf(a.z * inv + bb.z, 0.f);
    r.w = fmaxf(a.w * inv + bb.w, 0.f);
    *reinterpret_cast<float4*>(g_x2 + (size_t)n * NHID + 4 * v) = r;
    *reinterpret_cast<float4*>(g_acc2 + (size_t)n * NHID + 4 * v) =
        make_float4(0.f, 0.f, 0.f, 0.f);

    float4 wa = *reinterpret_cast<const float4*>(was + 4 * v);
    float4 wd = *reinterpret_cast<const float4*>(wad + 4 * v);
    float av = r.x * wa.x + r.y * wa.y + r.z * wa.z + r.w * wa.w;
    float dv = r.x * wd.x + r.y * wd.y + r.z * wd.z + r.w * wd.w;
    #pragma unroll
    for (int o = 4; o > 0; o >>= 1) {
        av += __shfl_xor_sync(0xffffffffu, av, o);
        dv += __shfl_xor_sync(0xffffffffu, dv, o);
    }
    if (v == 0) {
        g_asrc[n] = av; g_adst[n] = dv; g_denom2[n] = 0.f;
    }
}

// ---------------- finalize layer 2: matvec W2 + bias + log_softmax ----------
__global__ void finalize2_kernel(const float* __restrict__ W2,
                                 const float* __restrict__ b2,
                                 float* __restrict__ out) {
    __shared__ float Wsh[NHID * NCLASS];
    __shared__ float bsh[NCLASS];
    int tid = threadIdx.x;
    for (int i = tid; i < NHID * NCLASS; i += 256) Wsh[i] = W2[i];
    if (tid < NCLASS) bsh[tid] = b2[tid];
    __syncthreads();

    int lane = tid & 31, w = tid >> 5;
    int n = blockIdx.x * 8 + w;
    if (n >= N_NODES) return;
    float a = g_acc2[(size_t)n * NHID + lane] / (g_denom2[n] + 1e-16f);
    bool act1 = lane < 8;
    int c0 = lane;
    int c1 = act1 ? lane + 32 : 0;
    float y0 = 0.f, y1 = 0.f;
    #pragma unroll
    for (int k = 0; k < NHID; k++) {
        float ak = __shfl_sync(0xffffffffu, a, k);
        y0 += ak * Wsh[k * NCLASS + c0];
        y1 += ak * Wsh[k * NCLASS + c1];
    }
    y0 += bsh[c0];
    y1 += bsh[c1];
    float vm = act1 ? fmaxf(y0, y1) : y0;
    #pragma unroll
    for (int o = 16; o > 0; o >>= 1)
        vm = fmaxf(vm, __shfl_xor_sync(0xffffffffu, vm, o));
    float ssum = expf(y0 - vm) + (act1 ? expf(y1 - vm) : 0.f);
    #pragma unroll
    for (int o = 16; o > 0; o >>= 1)
        ssum += __shfl_xor_sync(0xffffffffu, ssum, o);
    float lse = vm + logf(ssum);
    out[n * NCLASS + c0] = y0 - lse;
    if (act1) out[n * NCLASS + 32 + lane] = y1 - lse;
}

// ---------------- launch ----------------------------------------------------
extern "C" void kernel_launch(void* const* d_in, const int* in_sizes, int n_in,
                              void* d_out, int out_size) {
    const float* x   = (const float*)d_in[0];
    const int*   ei  = (const int*)d_in[1];
    const float* W1  = (const float*)d_in[2];
    const float* as1 = (const float*)d_in[3];
    const float* ad1 = (const float*)d_in[4];
    const float* b1  = (const float*)d_in[5];
    const float* W2  = (const float*)d_in[6];
    const float* as2 = (const float*)d_in[7];
    const float* ad2 = (const float*)d_in[8];
    const float* b2  = (const float*)d_in[9];
    const int* src = ei;
    const int* dst = ei + N_EDGES;
    float* out = (float*)d_out;

    const int TPB = 256;
    int gemm1_grid = (N_NODES + 63) / 64;
    int eacc_grid  = ((N_EDGES / 2) * 8 + TPB - 1) / TPB;
    int fin1_grid  = (N_NODES + 31) / 32;
    int warp8_grid = (N_NODES + 7) / 8;

    // ---- layer 1 ----
    gemm1_kernel<<<gemm1_grid, TPB>>>(x, W1, as1, ad1);
    edge_accum_kernel<1><<<eacc_grid, TPB>>>(src, dst);
    finalize1_kernel<<<fin1_grid, TPB>>>(b1, W2, as2, ad2);

    // ---- layer 2 ----
    edge_accum_kernel<2><<<eacc_grid, TPB>>>(src, dst);
    finalize2_kernel<<<warp8_grid, TPB>>>(W2, b2, out);
}

// round 10
// speedup vs baseline: 1.9666x; 1.0613x over previous
#include <cuda_runtime.h>
#include <cuda_bf16.h>
#include <math.h>
#include <limits.h>

#define N_NODES 100000
#define N_EDGES 1600000
#define NFEAT 128
#define NHID 32
#define NCLASS 40
#define NEG_SLOPE 0.2f

// ---------------- scratch ----------------------------------------------------
__device__ __align__(16) float g_h1[N_NODES * NHID];
__device__ __align__(16) float g_acc1[N_NODES * NHID];
__device__ __align__(16) float g_x2[N_NODES * NHID];
__device__ __align__(16) float g_acc2[N_NODES * NHID];
__device__ float g_adst[N_NODES];
__device__ float g_denom1[N_NODES];
__device__ float g_denom2[N_NODES];
__device__ __align__(16) float g_was2[NHID];   // W2 @ a_src2
__device__ __align__(16) float g_wad2[NHID];   // W2 @ a_dst2

// ---------------- helpers ---------------------------------------------------
__device__ __forceinline__ float lrelu(float x) {
    return x > 0.f ? x : NEG_SLOPE * x;
}
__device__ __forceinline__ void red_add_v4(float* p, float4 v) {
    asm volatile("red.global.add.v4.f32 [%0], {%1,%2,%3,%4};"
                 :: "l"(p), "f"(v.x), "f"(v.y), "f"(v.z), "f"(v.w) : "memory");
}
__device__ __forceinline__ void red_add_f32(float* p, float v) {
    asm volatile("red.global.add.f32 [%0], %1;" :: "l"(p), "f"(v) : "memory");
}

// ---------------- prep: w_as2 = W2 @ a_src2, w_ad2 = W2 @ a_dst2 ------------
__global__ void prep2_kernel(const float* __restrict__ W2,
                             const float* __restrict__ as2,
                             const float* __restrict__ ad2) {
    int t = threadIdx.x;
    int k = t & 31;
    const float* a = (t < 32) ? as2 : ad2;
    float s = 0.f;
    #pragma unroll
    for (int c = 0; c < NCLASS; c++) s += W2[k * NCLASS + c] * a[c];
    if (t < 32) g_was2[k] = s;
    else        g_wad2[k] = s;
}

// ---------------- layer 1 GEMM: 64 nodes/block ------------------------------
// smem = 16KB (W) + 32KB (x tile) = 48KB static.
__global__ void gemm1_kernel(const float* __restrict__ x,
                             const float* __restrict__ W1,
                             const float* __restrict__ a_dst) {
    __shared__ float Wsh[NFEAT * NHID];
    __shared__ float xsh[64][NFEAT];
    int tid = threadIdx.x;
    int base = blockIdx.x * 64;

    const float4* W4 = reinterpret_cast<const float4*>(W1);
    float4* Wsh4 = reinterpret_cast<float4*>(Wsh);
    #pragma unroll
    for (int i = tid; i < NFEAT * NHID / 4; i += 256) Wsh4[i] = W4[i];
    const float4* x4 = reinterpret_cast<const float4*>(x);
    #pragma unroll
    for (int i = tid; i < 64 * NFEAT / 4; i += 256) {
        int r = i >> 5, cc = i & 31;
        if (base + r < N_NODES)
            reinterpret_cast<float4*>(&xsh[r][0])[cc] =
                x4[(size_t)(base + r) * (NFEAT / 4) + cc];
    }
    __syncthreads();

    int c = tid & 31, rr = tid >> 5;
    float adc = __ldg(&a_dst[c]);
    float acc[8];
    #pragma unroll
    for (int j = 0; j < 8; j++) acc[j] = 0.f;
    #pragma unroll 4
    for (int k = 0; k < NFEAT; k++) {
        float wk = Wsh[k * NHID + c];
        #pragma unroll
        for (int j = 0; j < 8; j++)
            acc[j] += xsh[rr + 8 * j][k] * wk;
    }
    #pragma unroll
    for (int j = 0; j < 8; j++) {
        int n = base + rr + 8 * j;
        if (n >= N_NODES) continue;
        g_h1[(size_t)n * NHID + c] = acc[j];
        g_acc1[(size_t)n * NHID + c] = 0.f;
        float dv = acc[j] * adc;
        #pragma unroll
        for (int o = 16; o > 0; o >>= 1)
            dv += __shfl_xor_sync(0xffffffffu, dv, o);
        if (c == 0) { g_adst[n] = dv; g_denom1[n] = 0.f; }
    }
}

// ---------------- edge pass: in-register alpha_src + fused exp + v4 scatter -
// 8 lanes per edge, 2 edges per thread. alpha_src computed from the gathered
// h row itself (dot with score vector, 3-level group shuffle).
// LAYER==1 uses the a_src1 input pointer; LAYER==2 reads g_was2 (device symbol
// must be resolved in DEVICE code, not passed from host!).
template <int LAYER>
__global__ void edge_accum_kernel(const int* __restrict__ src,
                                  const int* __restrict__ dst,
                                  const float* __restrict__ svec_in) {
    int t = blockIdx.x * blockDim.x + threadIdx.x;
    int v = t & 7;
    int p = t >> 3;                 // edge-pair index
    int e0 = p * 2;
    if (e0 >= N_EDGES) return;
    const float* __restrict__ h    = (LAYER == 1) ? g_h1     : g_x2;
    float* __restrict__       ac   = (LAYER == 1) ? g_acc1   : g_acc2;
    float* __restrict__       dnm  = (LAYER == 1) ? g_denom1 : g_denom2;
    const float* __restrict__ svec = (LAYER == 1) ? svec_in  : g_was2;

    int2 s2 = __ldg(reinterpret_cast<const int2*>(src) + p);
    int2 d2 = __ldg(reinterpret_cast<const int2*>(dst) + p);
    float4 sv = __ldg(reinterpret_cast<const float4*>(svec) + v);
    float ad0 = __ldg(&g_adst[d2.x]);
    float ad1 = __ldg(&g_adst[d2.y]);
    float4 h0 = __ldg(reinterpret_cast<const float4*>(h + (size_t)s2.x * NHID) + v);
    float4 h1 = __ldg(reinterpret_cast<const float4*>(h + (size_t)s2.y * NHID) + v);

    // alpha_src = h_row . svec  (group-of-8 reduction)
    float dot0 = h0.x * sv.x + h0.y * sv.y + h0.z * sv.z + h0.w * sv.w;
    float dot1 = h1.x * sv.x + h1.y * sv.y + h1.z * sv.z + h1.w * sv.w;
    #pragma unroll
    for (int o = 4; o > 0; o >>= 1) {
        dot0 += __shfl_xor_sync(0xffffffffu, dot0, o);
        dot1 += __shfl_xor_sync(0xffffffffu, dot1, o);
    }
    float ee0 = __expf(lrelu(dot0 + ad0));
    float ee1 = __expf(lrelu(dot1 + ad1));
    if (v == 0) {
        red_add_f32(&dnm[d2.x], ee0);
        red_add_f32(&dnm[d2.y], ee1);
    }
    h0.x *= ee0; h0.y *= ee0; h0.z *= ee0; h0.w *= ee0;
    h1.x *= ee1; h1.y *= ee1; h1.z *= ee1; h1.w *= ee1;
    red_add_v4(ac + (size_t)d2.x * NHID + 4 * v, h0);
    red_add_v4(ac + (size_t)d2.y * NHID + 4 * v, h1);
}

// ---------------- finalize layer 1 ------------------------------------------
__global__ void finalize1_kernel(const float* __restrict__ b1) {
    int tid = threadIdx.x;
    int g = tid >> 3, v = tid & 7;
    int n = blockIdx.x * 32 + g;
    if (n >= N_NODES) return;
    float inv = 1.f / (g_denom1[n] + 1e-16f);
    float4 a = *reinterpret_cast<const float4*>(g_acc1 + (size_t)n * NHID + 4 * v);
    float4 bb = __ldg(reinterpret_cast<const float4*>(b1) + v);
    float4 r;
    r.x = fmaxf(a.x * inv + bb.x, 0.f);
    r.y = fmaxf(a.y * inv + bb.y, 0.f);
    r.z = fmaxf(a.z * inv + bb.z, 0.f);
    r.w = fmaxf(a.w * inv + bb.w, 0.f);
    *reinterpret_cast<float4*>(g_x2 + (size_t)n * NHID + 4 * v) = r;
    *reinterpret_cast<float4*>(g_acc2 + (size_t)n * NHID + 4 * v) =
        make_float4(0.f, 0.f, 0.f, 0.f);

    float4 wd = *reinterpret_cast<const float4*>(g_wad2 + 4 * v);
    float dv = r.x * wd.x + r.y * wd.y + r.z * wd.z + r.w * wd.w;
    #pragma unroll
    for (int o = 4; o > 0; o >>= 1)
        dv += __shfl_xor_sync(0xffffffffu, dv, o);
    if (v == 0) { g_adst[n] = dv; g_denom2[n] = 0.f; }
}

// ---------------- finalize layer 2: matvec W2 + bias + log_softmax ----------
__global__ void finalize2_kernel(const float* __restrict__ W2,
                                 const float* __restrict__ b2,
                                 float* __restrict__ out) {
    __shared__ float Wsh[NHID * NCLASS];
    __shared__ float bsh[NCLASS];
    int tid = threadIdx.x;
    for (int i = tid; i < NHID * NCLASS; i += 256) Wsh[i] = W2[i];
    if (tid < NCLASS) bsh[tid] = b2[tid];
    __syncthreads();

    int lane = tid & 31, w = tid >> 5;
    int n = blockIdx.x * 8 + w;
    if (n >= N_NODES) return;
    float a = g_acc2[(size_t)n * NHID + lane] / (g_denom2[n] + 1e-16f);
    bool act1 = lane < 8;
    int c0 = lane;
    int c1 = act1 ? lane + 32 : 0;
    float y0 = 0.f, y1 = 0.f;
    #pragma unroll
    for (int k = 0; k < NHID; k++) {
        float ak = __shfl_sync(0xffffffffu, a, k);
        y0 += ak * Wsh[k * NCLASS + c0];
        y1 += ak * Wsh[k * NCLASS + c1];
    }
    y0 += bsh[c0];
    y1 += bsh[c1];
    float vm = act1 ? fmaxf(y0, y1) : y0;
    #pragma unroll
    for (int o = 16; o > 0; o >>= 1)
        vm = fmaxf(vm, __shfl_xor_sync(0xffffffffu, vm, o));
    float ssum = expf(y0 - vm) + (act1 ? expf(y1 - vm) : 0.f);
    #pragma unroll
    for (int o = 16; o > 0; o >>= 1)
        ssum += __shfl_xor_sync(0xffffffffu, ssum, o);
    float lse = vm + logf(ssum);
    out[n * NCLASS + c0] = y0 - lse;
    if (act1) out[n * NCLASS + 32 + lane] = y1 - lse;
}

// ---------------- launch ----------------------------------------------------
extern "C" void kernel_launch(void* const* d_in, const int* in_sizes, int n_in,
                              void* d_out, int out_size) {
    const float* x   = (const float*)d_in[0];
    const int*   ei  = (const int*)d_in[1];
    const float* W1  = (const float*)d_in[2];
    const float* as1 = (const float*)d_in[3];
    const float* ad1 = (const float*)d_in[4];
    const float* b1  = (const float*)d_in[5];
    const float* W2  = (const float*)d_in[6];
    const float* as2 = (const float*)d_in[7];
    const float* ad2 = (const float*)d_in[8];
    const float* b2  = (const float*)d_in[9];
    const int* src = ei;
    const int* dst = ei + N_EDGES;
    float* out = (float*)d_out;

    const int TPB = 256;
    int gemm1_grid = (N_NODES + 63) / 64;
    int eacc_grid  = ((N_EDGES / 2) * 8 + TPB - 1) / TPB;
    int fin1_grid  = (N_NODES + 31) / 32;
    int warp8_grid = (N_NODES + 7) / 8;

    prep2_kernel<<<1, 64>>>(W2, as2, ad2);

    // ---- layer 1 ----
    gemm1_kernel<<<gemm1_grid, TPB>>>(x, W1, ad1);
    edge_accum_kernel<1><<<eacc_grid, TPB>>>(src, dst, as1);
    finalize1_kernel<<<fin1_grid, TPB>>>(b1);

    // ---- layer 2 ----
    edge_accum_kernel<2><<<eacc_grid, TPB>>>(src, dst, nullptr);
    finalize2_kernel<<<warp8_grid, TPB>>>(W2, b2, out);
}